// round 16
// baseline (speedup 1.0000x reference)
#include <cuda_runtime.h>
#include <cuda_fp16.h>
#include <cstdint>

#define DI __device__ __forceinline__

// ---------------- scratch (static device globals; no runtime alloc) ----------------
__device__ __half g_X  [2048u*4096u];   // x single fp16 plane
__device__ __half g_Wt [6144u*4096u];   // [wq|wk|wv]^T single fp16 plane
__device__ __half g_WOt[4096u*4096u];   // wo^T single fp16 plane
__device__ __half g_Q  [2048u*4096u];   // post-rope, pre-scaled, single plane
__device__ __half g_K  [2048u*1024u];   // single plane
__device__ __half g_V  [2048u*1024u];   // single plane
__device__ __half g_AO [2048u*4096u];   // attention out, single plane
__device__ uint32_t g_job;              // persistent work counter (reset per launch)

// ---------------- helpers ----------------
DI uint32_t s_addr(const void* p){ return (uint32_t)__cvta_generic_to_shared(p); }

DI void ldm_x4(uint32_t a, uint32_t &r0, uint32_t &r1, uint32_t &r2, uint32_t &r3){
  asm volatile("ldmatrix.sync.aligned.m8n8.x4.shared.b16 {%0,%1,%2,%3}, [%4];\n"
               : "=r"(r0), "=r"(r1), "=r"(r2), "=r"(r3) : "r"(a));
}
DI void ldm_x4t(uint32_t a, uint32_t &r0, uint32_t &r1, uint32_t &r2, uint32_t &r3){
  asm volatile("ldmatrix.sync.aligned.m8n8.x4.trans.shared.b16 {%0,%1,%2,%3}, [%4];\n"
               : "=r"(r0), "=r"(r1), "=r"(r2), "=r"(r3) : "r"(a));
}
DI void mma_h(float c[4], const uint32_t a[4], const uint32_t b[2]){
  asm volatile("mma.sync.aligned.m16n8k16.row.col.f32.f16.f16.f32 "
               "{%0,%1,%2,%3}, {%4,%5,%6,%7}, {%8,%9}, {%0,%1,%2,%3};\n"
               : "+f"(c[0]), "+f"(c[1]), "+f"(c[2]), "+f"(c[3])
               : "r"(a[0]), "r"(a[1]), "r"(a[2]), "r"(a[3]), "r"(b[0]), "r"(b[1]));
}
DI uint32_t pk2h(__half a, __half b){
  __half2 t = __halves2half2(a, b);
  return *reinterpret_cast<uint32_t*>(&t);
}

// ---------------- async copy primitives ----------------
DI void cp16(uint32_t saddr, const void* gaddr){
  asm volatile("cp.async.cg.shared.global [%0], [%1], 16;" :: "r"(saddr), "l"(gaddr) : "memory");
}
DI void cp_commit(){ asm volatile("cp.async.commit_group;" ::: "memory"); }
DI void cp_wait0(){ asm volatile("cp.async.wait_group 0;" ::: "memory"); }
DI void cp_wait1(){ asm volatile("cp.async.wait_group 1;" ::: "memory"); }
DI void cp_wait2(){ asm volatile("cp.async.wait_group 2;" ::: "memory"); }

// =====================================================================
// conversion kernels (bandwidth-tuned: wide loads AND wide stores)
// =====================================================================
__global__ void conv_x(const float* __restrict__ x)
{
  int i = blockIdx.x*256 + threadIdx.x;   // 8-float index
  float4 v0 = reinterpret_cast<const float4*>(x)[i*2];
  float4 v1 = reinterpret_cast<const float4*>(x)[i*2 + 1];
  __half h[8];
  h[0] = __float2half_rn(v0.x); h[1] = __float2half_rn(v0.y);
  h[2] = __float2half_rn(v0.z); h[3] = __float2half_rn(v0.w);
  h[4] = __float2half_rn(v1.x); h[5] = __float2half_rn(v1.y);
  h[6] = __float2half_rn(v1.z); h[7] = __float2half_rn(v1.w);
  reinterpret_cast<uint4*>(g_X)[i] = *reinterpret_cast<uint4*>(h);
}

// transpose + round wq/wk/wv (wo is converted inside the QKV GEMM's job tail)
// grid.x ranges: [0,64) wq | [64,80) wk | [80,96) wv; grid.y = 64 k-blocks
__global__ void tconv_qkv(const float* __restrict__ wq, const float* __restrict__ wk,
                          const float* __restrict__ wv)
{
  __shared__ float t[64][65];
  const int tid = threadIdx.x;
  const int bx = blockIdx.x, k0 = blockIdx.y << 6;
  const float* src; __half* dst; int N, n0;
  if (bx < 64)      { src = wq; dst = g_Wt;                N = 4096; n0 = bx << 6; }
  else if (bx < 80) { src = wk; dst = g_Wt + 4096u*4096u;  N = 1024; n0 = (bx - 64) << 6; }
  else              { src = wv; dst = g_Wt + 5120u*4096u;  N = 1024; n0 = (bx - 80) << 6; }
  const int K = 4096;
  #pragma unroll
  for (int it = 0; it < 4; it++){         // load 64x64 floats as float4
    int idx = it*256 + tid;
    int r = idx >> 4, c4 = (idx & 15) << 2;
    float4 v = *reinterpret_cast<const float4*>(src + (size_t)(k0 + r)*N + n0 + c4);
    t[r][c4] = v.x; t[r][c4+1] = v.y; t[r][c4+2] = v.z; t[r][c4+3] = v.w;
  }
  __syncthreads();
  #pragma unroll
  for (int it = 0; it < 2; it++){         // store transposed as uint4 (8 halves)
    int idx = it*256 + tid;
    int n = idx >> 3, kg = (idx & 7) << 3;
    __half h[8];
    #pragma unroll
    for (int q = 0; q < 8; q++) h[q] = __float2half_rn(t[kg + q][n]);
    *reinterpret_cast<uint4*>(dst + (size_t)(n0 + n)*K + k0 + kg) =
        *reinterpret_cast<uint4*>(h);
  }
}

// =====================================================================
// Persistent GEMM: C[M,N] = A(fp16)[M,K] * B(fp16)[N,K]^T, fp32 acc.
// 296 CTAs pull 128x128 tile jobs from g_job (uniform jobs, greedy schedule).
// 256 threads = 8 warps (4m x 2n), warp tile 32x64, k-tile 32.
// 4-stage cp.async ring; OCCUPANCY 2 (smem ~81952B, regs capped at 128).
// MODE 0: plain fp32 C store.  MODE 1: fused RoPE + fp16 -> Q/K/V planes,
//   plus job-tail wo transpose-convert (jobs >= ngemm, 64x64 tiles).
// =====================================================================
#define GROWB 80
#define APLANE (128*GROWB)         // 10240 B
#define BPLANE (128*GROWB)         // 10240 B
#define GSTG   (APLANE + BPLANE)   // 20480 B
#define GEMM_SMEM (4*GSTG + 16)    // 81936 B  (x2 CTAs <= 227K)

template<int MODE>
__global__ void __launch_bounds__(256, 2) gemm_ca(
    const __half* __restrict__ Ah, const __half* __restrict__ Bh,
    float* __restrict__ C, const float* __restrict__ fc,
    const float* __restrict__ wosrc,
    int N, int K, int njobs, int ngemm, int nx)
{
  extern __shared__ char smem[];
  const uint32_t sb = s_addr(smem);
  uint32_t* sjob = reinterpret_cast<uint32_t*>(smem + 4*GSTG);
  const int tid = threadIdx.x, lane = tid & 31, warp = tid >> 5;
  const int wm = warp >> 1, wn = warp & 1;
  const int T = K >> 5;
  const int g = lane >> 2, tq = lane & 3;

  for (;;){
    if (tid == 0) *sjob = atomicAdd(&g_job, 1u);
    __syncthreads();
    const uint32_t j = *sjob;
    if (j >= (uint32_t)njobs) break;

    if (MODE == 1 && j >= (uint32_t)ngemm){
      // ---- tail job: wo transpose-convert, one 64x64 tile ----
      const uint32_t jc = j - (uint32_t)ngemm;
      const int n0 = (int)(jc >> 6) << 6, k0 = (int)(jc & 63) << 6;
      float (*t)[65] = reinterpret_cast<float(*)[65]>(smem);
      #pragma unroll
      for (int it = 0; it < 4; it++){
        int idx = it*256 + tid;
        int r = idx >> 4, c4 = (idx & 15) << 2;
        float4 v = *reinterpret_cast<const float4*>(wosrc + (size_t)(k0 + r)*4096 + n0 + c4);
        t[r][c4] = v.x; t[r][c4+1] = v.y; t[r][c4+2] = v.z; t[r][c4+3] = v.w;
      }
      __syncthreads();
      #pragma unroll
      for (int it = 0; it < 2; it++){
        int idx = it*256 + tid;
        int n = idx >> 3, kg = (idx & 7) << 3;
        __half h[8];
        #pragma unroll
        for (int q = 0; q < 8; q++) h[q] = __float2half_rn(t[kg + q][n]);
        *reinterpret_cast<uint4*>(g_WOt + (size_t)(n0 + n)*4096 + k0 + kg) =
            *reinterpret_cast<uint4*>(h);
      }
      continue;   // fetch-point syncthreads orders smem reuse
    }

    const int m0 = (int)(j / nx) * 128, n0 = (int)(j % nx) * 128;

    float acc[2][8][4];
    #pragma unroll
    for (int i = 0; i < 2; i++)
      #pragma unroll
      for (int jj = 0; jj < 8; jj++)
        #pragma unroll
        for (int k = 0; k < 4; k++) acc[i][jj][k] = 0.f;

    auto issue = [&](int t){
      const uint32_t s0 = sb + (uint32_t)(t & 3)*GSTG;
      const int kb = t << 5;
      #pragma unroll
      for (int i = 0; i < 2; i++){   // A: 128 rows x 4 chunks = 512 ops
        int idx = i*256 + tid;
        int r = (idx >> 2) & 127, c = idx & 3;
        cp16(s0 + r*GROWB + c*16, Ah + (size_t)(m0 + r)*K + kb + c*8);
      }
      #pragma unroll
      for (int i = 0; i < 2; i++){   // B: 128 rows x 4 chunks = 512 ops
        int idx = i*256 + tid;
        int r = (idx >> 2) & 127, c = idx & 3;
        cp16(s0 + APLANE + r*GROWB + c*16, Bh + (size_t)(n0 + r)*K + kb + c*8);
      }
    };

    issue(0); cp_commit();
    issue(1); cp_commit();
    issue(2); cp_commit();

    for (int t = 0; t < T; t++){
      cp_wait2();
      __syncthreads();
      if (t + 3 < T) issue(t + 3);
      cp_commit();
      const uint32_t s0 = sb + (uint32_t)(t & 3)*GSTG;
      const uint32_t aB = s0, bB = s0 + APLANE;
      #pragma unroll
      for (int ks = 0; ks < 2; ks++){
        uint32_t ah[2][4];
        #pragma unroll
        for (int wmi = 0; wmi < 2; wmi++){
          uint32_t off = (uint32_t)(wm*32 + wmi*16 + (lane & 15))*GROWB + ks*32 + ((lane >> 4) << 4);
          ldm_x4(aB + off, ah[wmi][0], ah[wmi][1], ah[wmi][2], ah[wmi][3]);
        }
        const int nr = wn*64 + (lane & 7) + ((lane >> 4) << 3);
        const uint32_t ccb = ks*32 + (((lane >> 3) & 1) << 4);
        #pragma unroll
        for (int g4 = 0; g4 < 4; g4++){
          uint32_t bh[2][2];
          uint32_t off = (uint32_t)(nr + g4*16)*GROWB + ccb;
          ldm_x4(bB + off, bh[0][0], bh[0][1], bh[1][0], bh[1][1]);
          #pragma unroll
          for (int wmi = 0; wmi < 2; wmi++)
            #pragma unroll
            for (int jj = 0; jj < 2; jj++) mma_h(acc[wmi][g4*2 + jj], ah[wmi], bh[jj]);
        }
      }
      // no end-of-loop sync: next iteration's cp_wait + syncthreads orders the
      // t+4 overwrite of buf t%4 against all threads' compute(t). Across job
      // boundaries all data-bearing groups are complete (pending = empties).
    }

    // fused RoPE + fp16 writer for one fp32 pair at (row, c even)
    auto emit = [&](int row, int c, float a, float b){
      if (c < 4096){
        float2 f = *reinterpret_cast<const float2*>(fc + (size_t)row*128 + (c & 127));
        const float sc = 0.08838834764831845f;   // 128^-0.5
        *reinterpret_cast<uint32_t*>(&g_Q[(size_t)row*4096 + c]) =
            pk2h(__float2half_rn((a*f.x - b*f.y)*sc), __float2half_rn((a*f.y + b*f.x)*sc));
      } else if (c < 5120){
        float2 f = *reinterpret_cast<const float2*>(fc + (size_t)row*128 + (c & 127));
        *reinterpret_cast<uint32_t*>(&g_K[(size_t)row*1024 + c - 4096]) =
            pk2h(__float2half_rn(a*f.x - b*f.y), __float2half_rn(a*f.y + b*f.x));
      } else {
        *reinterpret_cast<uint32_t*>(&g_V[(size_t)row*1024 + c - 5120]) =
            pk2h(__float2half_rn(a), __float2half_rn(b));
      }
    };

    #pragma unroll
    for (int wmi = 0; wmi < 2; wmi++){
      int r = m0 + wm*32 + wmi*16 + g;
      #pragma unroll
      for (int nt = 0; nt < 8; nt++){
        int c = n0 + wn*64 + nt*8 + tq*2;
        if (MODE == 0){
          float2 v0 = make_float2(acc[wmi][nt][0], acc[wmi][nt][1]);
          float2 v1 = make_float2(acc[wmi][nt][2], acc[wmi][nt][3]);
          *reinterpret_cast<float2*>(C + (size_t)r*N + c)     = v0;
          *reinterpret_cast<float2*>(C + (size_t)(r+8)*N + c) = v1;
        } else {
          emit(r,     c, acc[wmi][nt][0], acc[wmi][nt][1]);
          emit(r + 8, c, acc[wmi][nt][2], acc[wmi][nt][3]);
        }
      }
    }
    // loop back: job fetch does __syncthreads before any smem ring reuse
  }
}

// =====================================================================
// Persistent causal flash attention. 148 CTAs pull (qt, h) jobs from g_job,
// heaviest q-tiles first (LPT). Per job: 128 q rows x 1 head, 8 warps x 16
// rows, KV tiles of 64, 3-stage cp.async ring. QK^T and PV single pass fp16.
// Row = 128 fp16 = 256 B + 16 pad = 272 B stride (17 x 16B -> conflict-free).
// =====================================================================
#define FROWB 272
#define FPLANE (64*FROWB)          // 17408 B
#define FSTAGE (2*FPLANE)          // 34816 B (K plane + V plane)
#define FLASH_SMEM (3*FSTAGE + 16) // 104464 B (16 B for job broadcast)
#define NJOBS 512

__global__ void __launch_bounds__(256) flash_kernel()
{
  extern __shared__ char smem[];
  const uint32_t sb = s_addr(smem);
  uint32_t* sjob = reinterpret_cast<uint32_t*>(smem + 3*FSTAGE);
  const int tid = threadIdx.x, lane = tid & 31, warp = tid >> 5;
  const int g = lane >> 2, t4 = lane & 3;

  for (;;){
    if (tid == 0) *sjob = atomicAdd(&g_job, 1u);
    __syncthreads();
    const uint32_t j = *sjob;
    if (j >= NJOBS) break;
    const int qt = 15 - (int)(j >> 5);       // heavy tiles first (LPT)
    const int h  = (int)(j & 31);
    const int q0 = qt*128, kvh = h >> 2;

    // ---- stage Q plane (128 rows x 256 B = 32768 B, fits ring buf 0) ----
    #pragma unroll
    for (int i = 0; i < 8; i++){
      int idx = i*256 + tid;
      int r = idx >> 4, c = idx & 15;
      const __half* src = g_Q + (size_t)(q0 + r)*4096 + h*128 + c*8;
      *reinterpret_cast<uint4*>(smem + r*FROWB + c*16) =
          *reinterpret_cast<const uint4*>(src);
    }
    __syncthreads();

    uint32_t qh[8][4];
    {
      uint32_t rowb = (uint32_t)(warp*16 + (lane & 15))*FROWB + ((lane >> 4) << 4);
      #pragma unroll
      for (int kk = 0; kk < 8; kk++)
        ldm_x4(sb + rowb + kk*32, qh[kk][0], qh[kk][1], qh[kk][2], qh[kk][3]);
    }
    __syncthreads();   // all Q reads done before cp.async reuses buffer 0

    float o[16][4];
    #pragma unroll
    for (int i = 0; i < 16; i++){ o[i][0]=0.f; o[i][1]=0.f; o[i][2]=0.f; o[i][3]=0.f; }
    float rm0 = -1e30f, rm1 = -1e30f;
    float rl0 = 0.f,    rl1 = 0.f;

    const int nkv = qt*2 + 2;

    auto issue = [&](int kt){
      const uint32_t s0 = sb + (uint32_t)(kt % 3)*FSTAGE;
      const int kv0 = kt*64;
      #pragma unroll
      for (int i = 0; i < 8; i++){   // K,V: 2 planes x 64 rows x 16 chunks
        int idx = i*256 + tid;
        int p = idx >> 10, r = (idx >> 4) & 63, c = idx & 15;
        const __half* base = p ? g_V : g_K;
        cp16(s0 + (uint32_t)p*FPLANE + r*FROWB + c*16,
             base + (size_t)(kv0 + r)*1024 + kvh*128 + c*8);
      }
    };

    issue(0); cp_commit();
    issue(1); cp_commit();

    for (int kvt = 0; kvt < nkv; kvt++){
      const int kv0 = kvt*64;
      cp_wait1();
      __syncthreads();
      if (kvt + 2 < nkv) issue(kvt + 2);   // prefetch BEFORE compute
      cp_commit();
      const uint32_t s0 = sb + (uint32_t)(kvt % 3)*FSTAGE;
      const uint32_t kB = s0, vB = s0 + FPLANE;

      // ---- S = Q K^T (single pass) ----
      float s[8][4];
      #pragma unroll
      for (int i = 0; i < 8; i++){ s[i][0]=0.f; s[i][1]=0.f; s[i][2]=0.f; s[i][3]=0.f; }
      {
        const int nr = (lane & 7) + ((lane >> 4) << 3);
        #pragma unroll
        for (int kk = 0; kk < 8; kk++){
          const uint32_t ccb = kk*32 + (((lane >> 3) & 1) << 4);
          #pragma unroll
          for (int g4 = 0; g4 < 4; g4++){
            uint32_t bh[2][2];
            uint32_t off = (uint32_t)(g4*16 + nr)*FROWB + ccb;
            ldm_x4(kB + off, bh[0][0], bh[0][1], bh[1][0], bh[1][1]);
            mma_h(s[g4*2],     qh[kk], bh[0]);
            mma_h(s[g4*2 + 1], qh[kk], bh[1]);
          }
        }
      }

      // ---- causal mask ----
      if (kv0 + 63 > q0 + warp*16){
        #pragma unroll
        for (int nt = 0; nt < 8; nt++){
          int kvb = kv0 + nt*8 + t4*2;
          #pragma unroll
          for (int jj = 0; jj < 4; jj++){
            int kv = kvb + (jj & 1);
            int rw = q0 + warp*16 + g + ((jj >> 1) << 3);
            if (kv > rw) s[nt][jj] = -1e30f;
          }
        }
      }

      // ---- online softmax ----
      float mt0 = -1e30f, mt1 = -1e30f;
      #pragma unroll
      for (int nt = 0; nt < 8; nt++){
        mt0 = fmaxf(mt0, fmaxf(s[nt][0], s[nt][1]));
        mt1 = fmaxf(mt1, fmaxf(s[nt][2], s[nt][3]));
      }
      mt0 = fmaxf(mt0, __shfl_xor_sync(0xffffffffu, mt0, 1));
      mt0 = fmaxf(mt0, __shfl_xor_sync(0xffffffffu, mt0, 2));
      mt1 = fmaxf(mt1, __shfl_xor_sync(0xffffffffu, mt1, 1));
      mt1 = fmaxf(mt1, __shfl_xor_sync(0xffffffffu, mt1, 2));
      float mn0 = fmaxf(rm0, mt0), mn1 = fmaxf(rm1, mt1);
      float f0 = __expf(rm0 - mn0), f1 = __expf(rm1 - mn1);
      rm0 = mn0; rm1 = mn1;
      float ps0 = 0.f, ps1 = 0.f;
      #pragma unroll
      for (int nt = 0; nt < 8; nt++){
        s[nt][0] = __expf(s[nt][0] - mn0); ps0 += s[nt][0];
        s[nt][1] = __expf(s[nt][1] - mn0); ps0 += s[nt][1];
        s[nt][2] = __expf(s[nt][2] - mn1); ps1 += s[nt][2];
        s[nt][3] = __expf(s[nt][3] - mn1); ps1 += s[nt][3];
      }
      rl0 = rl0*f0 + ps0;
      rl1 = rl1*f1 + ps1;
      #pragma unroll
      for (int d = 0; d < 16; d++){
        o[d][0] *= f0; o[d][1] *= f0; o[d][2] *= f1; o[d][3] *= f1;
      }

      // ---- repack P as fp16x2 A-fragments (registers) ----
      uint32_t pah[4][4];
      #pragma unroll
      for (int k2 = 0; k2 < 4; k2++){
        pah[k2][0] = pk2h(__float2half_rn(s[2*k2][0]),   __float2half_rn(s[2*k2][1]));
        pah[k2][1] = pk2h(__float2half_rn(s[2*k2][2]),   __float2half_rn(s[2*k2][3]));
        pah[k2][2] = pk2h(__float2half_rn(s[2*k2+1][0]), __float2half_rn(s[2*k2+1][1]));
        pah[k2][3] = pk2h(__float2half_rn(s[2*k2+1][2]), __float2half_rn(s[2*k2+1][3]));
      }

      // ---- O += P V (single pass) ----
      #pragma unroll
      for (int k2 = 0; k2 < 4; k2++){
        uint32_t vrowb = (uint32_t)(k2*16 + (lane & 7) + (((lane >> 3) & 1) << 3))*FROWB
                       + (((lane >> 4) & 1) << 4);
        #pragma unroll
        for (int dg = 0; dg < 8; dg++){
          uint32_t vh[2][2];
          ldm_x4t(vB + vrowb + dg*32, vh[0][0], vh[0][1], vh[1][0], vh[1][1]);
          mma_h(o[dg*2],     pah[k2], vh[0]);
          mma_h(o[dg*2 + 1], pah[k2], vh[1]);
        }
      }
      // no end-of-loop sync: next iteration's cp_wait + syncthreads orders the
      // kvt+3 overwrite of buf kvt%3 against all threads' compute(kvt).
    }

    // ---- finalize: O /= l, write single fp16 plane ----
    rl0 += __shfl_xor_sync(0xffffffffu, rl0, 1);
    rl0 += __shfl_xor_sync(0xffffffffu, rl0, 2);
    rl1 += __shfl_xor_sync(0xffffffffu, rl1, 1);
    rl1 += __shfl_xor_sync(0xffffffffu, rl1, 2);
    float inv0 = 1.f/rl0, inv1 = 1.f/rl1;
    int row = q0 + warp*16 + g;
    #pragma unroll
    for (int dg = 0; dg < 16; dg++){
      int c = h*128 + dg*8 + t4*2;
      uint32_t ph0 = pk2h(__float2half_rn(o[dg][0]*inv0), __float2half_rn(o[dg][1]*inv0));
      uint32_t ph1 = pk2h(__float2half_rn(o[dg][2]*inv1), __float2half_rn(o[dg][3]*inv1));
      *reinterpret_cast<uint32_t*>(&g_AO[(size_t)row*4096 + c])     = ph0;
      *reinterpret_cast<uint32_t*>(&g_AO[(size_t)(row+8)*4096 + c]) = ph1;
    }

    cp_wait0();          // drain pending (empty) groups before next job
    __syncthreads();     // all smem reads done before next job's Q staging
  }
}

// =====================================================================
// launch
// =====================================================================
extern "C" void kernel_launch(void* const* d_in, const int* in_sizes, int n_in,
                              void* d_out, int out_size)
{
  (void)in_sizes; (void)n_in; (void)out_size;
  const float* x  = (const float*)d_in[0];
  const float* fc = (const float*)d_in[2];
  const float* wq = (const float*)d_in[3];
  const float* wk = (const float*)d_in[4];
  const float* wv = (const float*)d_in[5];
  const float* wo = (const float*)d_in[6];
  float* out = (float*)d_out;

  __half *X, *Wt, *WOt, *AO;
  void* jobp;
  cudaGetSymbolAddress((void**)&X,   g_X);
  cudaGetSymbolAddress((void**)&Wt,  g_Wt);
  cudaGetSymbolAddress((void**)&WOt, g_WOt);
  cudaGetSymbolAddress((void**)&AO,  g_AO);
  cudaGetSymbolAddress(&jobp, g_job);

  cudaFuncSetAttribute(gemm_ca<0>, cudaFuncAttributeMaxDynamicSharedMemorySize, GEMM_SMEM);
  cudaFuncSetAttribute(gemm_ca<1>, cudaFuncAttributeMaxDynamicSharedMemorySize, GEMM_SMEM);
  cudaFuncSetAttribute(flash_kernel, cudaFuncAttributeMaxDynamicSharedMemorySize, FLASH_SMEM);

  // conversions (wo is converted inside the QKV GEMM's job tail)
  conv_x<<<4096, 256>>>(x);
  tconv_qkv<<<dim3(96, 64), 256>>>(wq, wk, wv);

  // fused QKV projection + RoPE + fp16 convert, then wo-convert tail jobs
  cudaMemsetAsync(jobp, 0, sizeof(uint32_t));
  gemm_ca<1><<<296, 256, GEMM_SMEM>>>(X, Wt, nullptr, fc, wo, 6144, 4096,
                                      768 + 4096, 768, 48);

  // persistent attention
  cudaMemsetAsync(jobp, 0, sizeof(uint32_t));
  flash_kernel<<<148, 256, FLASH_SMEM>>>();

  // output projection
  cudaMemsetAsync(jobp, 0, sizeof(uint32_t));
  gemm_ca<0><<<296, 256, GEMM_SMEM>>>(AO, WOt, out, nullptr, nullptr, 4096, 4096,
                                      512, 512, 32);
}

// round 17
// speedup vs baseline: 1.0458x; 1.0458x over previous
#include <cuda_runtime.h>
#include <cuda_fp16.h>
#include <cstdint>

#define DI __device__ __forceinline__

// ---------------- scratch (static device globals; no runtime alloc) ----------------
__device__ __half g_X  [2048u*4096u];   // x single fp16 plane
__device__ __half g_Wt [6144u*4096u];   // [wq|wk|wv]^T single fp16 plane
__device__ __half g_WOt[4096u*4096u];   // wo^T single fp16 plane
__device__ __half g_Q  [2048u*4096u];   // post-rope, pre-scaled, single plane
__device__ __half g_K  [2048u*1024u];   // single plane
__device__ __half g_V  [2048u*1024u];   // single plane
__device__ __half g_AO [2048u*4096u];   // attention out, single plane
__device__ uint32_t g_job;              // persistent work counter (reset per launch)

// ---------------- helpers ----------------
DI uint32_t s_addr(const void* p){ return (uint32_t)__cvta_generic_to_shared(p); }

DI void ldm_x4(uint32_t a, uint32_t &r0, uint32_t &r1, uint32_t &r2, uint32_t &r3){
  asm volatile("ldmatrix.sync.aligned.m8n8.x4.shared.b16 {%0,%1,%2,%3}, [%4];\n"
               : "=r"(r0), "=r"(r1), "=r"(r2), "=r"(r3) : "r"(a));
}
DI void ldm_x4t(uint32_t a, uint32_t &r0, uint32_t &r1, uint32_t &r2, uint32_t &r3){
  asm volatile("ldmatrix.sync.aligned.m8n8.x4.trans.shared.b16 {%0,%1,%2,%3}, [%4];\n"
               : "=r"(r0), "=r"(r1), "=r"(r2), "=r"(r3) : "r"(a));
}
DI void mma_h(float c[4], const uint32_t a[4], const uint32_t b[2]){
  asm volatile("mma.sync.aligned.m16n8k16.row.col.f32.f16.f16.f32 "
               "{%0,%1,%2,%3}, {%4,%5,%6,%7}, {%8,%9}, {%0,%1,%2,%3};\n"
               : "+f"(c[0]), "+f"(c[1]), "+f"(c[2]), "+f"(c[3])
               : "r"(a[0]), "r"(a[1]), "r"(a[2]), "r"(a[3]), "r"(b[0]), "r"(b[1]));
}
DI uint32_t pk2h(__half a, __half b){
  __half2 t = __halves2half2(a, b);
  return *reinterpret_cast<uint32_t*>(&t);
}

// ---------------- async copy primitives ----------------
DI void cp16(uint32_t saddr, const void* gaddr){
  asm volatile("cp.async.cg.shared.global [%0], [%1], 16;" :: "r"(saddr), "l"(gaddr) : "memory");
}
DI void cp_commit(){ asm volatile("cp.async.commit_group;" ::: "memory"); }
DI void cp_wait0(){ asm volatile("cp.async.wait_group 0;" ::: "memory"); }
DI void cp_wait1(){ asm volatile("cp.async.wait_group 1;" ::: "memory"); }
DI void cp_wait2(){ asm volatile("cp.async.wait_group 2;" ::: "memory"); }

// =====================================================================
// conversion kernels (bandwidth-tuned: wide loads AND wide stores)
// =====================================================================
__global__ void conv_x(const float* __restrict__ x)
{
  int i = blockIdx.x*256 + threadIdx.x;   // 8-float index
  float4 v0 = reinterpret_cast<const float4*>(x)[i*2];
  float4 v1 = reinterpret_cast<const float4*>(x)[i*2 + 1];
  __half h[8];
  h[0] = __float2half_rn(v0.x); h[1] = __float2half_rn(v0.y);
  h[2] = __float2half_rn(v0.z); h[3] = __float2half_rn(v0.w);
  h[4] = __float2half_rn(v1.x); h[5] = __float2half_rn(v1.y);
  h[6] = __float2half_rn(v1.z); h[7] = __float2half_rn(v1.w);
  reinterpret_cast<uint4*>(g_X)[i] = *reinterpret_cast<uint4*>(h);
}

// transpose + round all four weights in one launch: fp32 [K,N] -> fp16 [N,K]
// grid.x ranges: [0,64) wq | [64,80) wk | [80,96) wv | [96,160) wo; grid.y = 64
__global__ void tconv_all(const float* __restrict__ wq, const float* __restrict__ wk,
                          const float* __restrict__ wv, const float* __restrict__ wo)
{
  __shared__ float t[64][65];
  const int tid = threadIdx.x;
  const int bx = blockIdx.x, k0 = blockIdx.y << 6;
  const float* src; __half* dst; int N, n0;
  if (bx < 64)      { src = wq; dst = g_Wt;                N = 4096; n0 = bx << 6; }
  else if (bx < 80) { src = wk; dst = g_Wt + 4096u*4096u;  N = 1024; n0 = (bx - 64) << 6; }
  else if (bx < 96) { src = wv; dst = g_Wt + 5120u*4096u;  N = 1024; n0 = (bx - 80) << 6; }
  else              { src = wo; dst = g_WOt;               N = 4096; n0 = (bx - 96) << 6; }
  const int K = 4096;
  #pragma unroll
  for (int it = 0; it < 4; it++){         // load 64x64 floats as float4
    int idx = it*256 + tid;
    int r = idx >> 4, c4 = (idx & 15) << 2;
    float4 v = *reinterpret_cast<const float4*>(src + (size_t)(k0 + r)*N + n0 + c4);
    t[r][c4] = v.x; t[r][c4+1] = v.y; t[r][c4+2] = v.z; t[r][c4+3] = v.w;
  }
  __syncthreads();
  #pragma unroll
  for (int it = 0; it < 2; it++){         // store transposed as uint4 (8 halves)
    int idx = it*256 + tid;
    int n = idx >> 3, kg = (idx & 7) << 3;
    __half h[8];
    #pragma unroll
    for (int q = 0; q < 8; q++) h[q] = __float2half_rn(t[kg + q][n]);
    *reinterpret_cast<uint4*>(dst + (size_t)(n0 + n)*K + k0 + kg) =
        *reinterpret_cast<uint4*>(h);
  }
}

// =====================================================================
// Persistent GEMM: C[M,N] = A(fp16)[M,K] * B(fp16)[N,K]^T, fp32 acc.
// 296 CTAs pull 128x128 tile jobs from g_job (uniform jobs, greedy schedule).
// 256 threads = 8 warps (4m x 2n), warp tile 32x64, k-tile 32.
// 4-stage cp.async ring; OCCUPANCY 2 (smem ~81952B, regs capped at 128).
// MODE 0: plain fp32 C store.  MODE 1: fused RoPE + fp16 -> Q/K/V planes.
// =====================================================================
#define GROWB 80
#define APLANE (128*GROWB)         // 10240 B
#define BPLANE (128*GROWB)         // 10240 B
#define GSTG   (APLANE + BPLANE)   // 20480 B
#define GEMM_SMEM (4*GSTG + 16)    // 81936 B  (x2 CTAs <= 227K)

template<int MODE>
__global__ void __launch_bounds__(256, 2) gemm_ca(
    const __half* __restrict__ Ah, const __half* __restrict__ Bh,
    float* __restrict__ C, const float* __restrict__ fc,
    int N, int K, int njobs, int nx)
{
  extern __shared__ char smem[];
  const uint32_t sb = s_addr(smem);
  uint32_t* sjob = reinterpret_cast<uint32_t*>(smem + 4*GSTG);
  const int tid = threadIdx.x, lane = tid & 31, warp = tid >> 5;
  const int wm = warp >> 1, wn = warp & 1;
  const int T = K >> 5;
  const int g = lane >> 2, tq = lane & 3;

  for (;;){
    if (tid == 0) *sjob = atomicAdd(&g_job, 1u);
    __syncthreads();
    const uint32_t j = *sjob;
    if (j >= (uint32_t)njobs) break;
    const int m0 = (int)(j / nx) * 128, n0 = (int)(j % nx) * 128;

    float acc[2][8][4];
    #pragma unroll
    for (int i = 0; i < 2; i++)
      #pragma unroll
      for (int jj = 0; jj < 8; jj++)
        #pragma unroll
        for (int k = 0; k < 4; k++) acc[i][jj][k] = 0.f;

    auto issue = [&](int t){
      const uint32_t s0 = sb + (uint32_t)(t & 3)*GSTG;
      const int kb = t << 5;
      #pragma unroll
      for (int i = 0; i < 2; i++){   // A: 128 rows x 4 chunks = 512 ops
        int idx = i*256 + tid;
        int r = (idx >> 2) & 127, c = idx & 3;
        cp16(s0 + r*GROWB + c*16, Ah + (size_t)(m0 + r)*K + kb + c*8);
      }
      #pragma unroll
      for (int i = 0; i < 2; i++){   // B: 128 rows x 4 chunks = 512 ops
        int idx = i*256 + tid;
        int r = (idx >> 2) & 127, c = idx & 3;
        cp16(s0 + APLANE + r*GROWB + c*16, Bh + (size_t)(n0 + r)*K + kb + c*8);
      }
    };

    issue(0); cp_commit();
    issue(1); cp_commit();
    issue(2); cp_commit();

    for (int t = 0; t < T; t++){
      cp_wait2();
      __syncthreads();
      if (t + 3 < T) issue(t + 3);
      cp_commit();
      const uint32_t s0 = sb + (uint32_t)(t & 3)*GSTG;
      const uint32_t aB = s0, bB = s0 + APLANE;
      #pragma unroll
      for (int ks = 0; ks < 2; ks++){
        uint32_t ah[2][4];
        #pragma unroll
        for (int wmi = 0; wmi < 2; wmi++){
          uint32_t off = (uint32_t)(wm*32 + wmi*16 + (lane & 15))*GROWB + ks*32 + ((lane >> 4) << 4);
          ldm_x4(aB + off, ah[wmi][0], ah[wmi][1], ah[wmi][2], ah[wmi][3]);
        }
        const int nr = wn*64 + (lane & 7) + ((lane >> 4) << 3);
        const uint32_t ccb = ks*32 + (((lane >> 3) & 1) << 4);
        #pragma unroll
        for (int g4 = 0; g4 < 4; g4++){
          uint32_t bh[2][2];
          uint32_t off = (uint32_t)(nr + g4*16)*GROWB + ccb;
          ldm_x4(bB + off, bh[0][0], bh[0][1], bh[1][0], bh[1][1]);
          #pragma unroll
          for (int wmi = 0; wmi < 2; wmi++)
            #pragma unroll
            for (int jj = 0; jj < 2; jj++) mma_h(acc[wmi][g4*2 + jj], ah[wmi], bh[jj]);
        }
      }
      // no end-of-loop sync: next iteration's cp_wait + syncthreads orders the
      // t+4 overwrite of buf t%4 against all threads' compute(t). Across job
      // boundaries all data-bearing groups are complete (pending = empties).
    }

    // fused RoPE + fp16 writer for one fp32 pair at (row, c even)
    auto emit = [&](int row, int c, float a, float b){
      if (c < 4096){
        float2 f = *reinterpret_cast<const float2*>(fc + (size_t)row*128 + (c & 127));
        const float sc = 0.08838834764831845f;   // 128^-0.5
        *reinterpret_cast<uint32_t*>(&g_Q[(size_t)row*4096 + c]) =
            pk2h(__float2half_rn((a*f.x - b*f.y)*sc), __float2half_rn((a*f.y + b*f.x)*sc));
      } else if (c < 5120){
        float2 f = *reinterpret_cast<const float2*>(fc + (size_t)row*128 + (c & 127));
        *reinterpret_cast<uint32_t*>(&g_K[(size_t)row*1024 + c - 4096]) =
            pk2h(__float2half_rn(a*f.x - b*f.y), __float2half_rn(a*f.y + b*f.x));
      } else {
        *reinterpret_cast<uint32_t*>(&g_V[(size_t)row*1024 + c - 5120]) =
            pk2h(__float2half_rn(a), __float2half_rn(b));
      }
    };

    #pragma unroll
    for (int wmi = 0; wmi < 2; wmi++){
      int r = m0 + wm*32 + wmi*16 + g;
      #pragma unroll
      for (int nt = 0; nt < 8; nt++){
        int c = n0 + wn*64 + nt*8 + tq*2;
        if (MODE == 0){
          float2 v0 = make_float2(acc[wmi][nt][0], acc[wmi][nt][1]);
          float2 v1 = make_float2(acc[wmi][nt][2], acc[wmi][nt][3]);
          *reinterpret_cast<float2*>(C + (size_t)r*N + c)     = v0;
          *reinterpret_cast<float2*>(C + (size_t)(r+8)*N + c) = v1;
        } else {
          emit(r,     c, acc[wmi][nt][0], acc[wmi][nt][1]);
          emit(r + 8, c, acc[wmi][nt][2], acc[wmi][nt][3]);
        }
      }
    }
    // loop back: job fetch does __syncthreads before any smem ring reuse
  }
}

// =====================================================================
// Persistent causal flash attention. 148 CTAs pull (qt, h) jobs from g_job,
// heaviest q-tiles first (LPT). Per job: 128 q rows x 1 head, 8 warps x 16
// rows, KV tiles of 128 (halved loop overhead, identical total mma work),
// 3-stage cp.async ring. QK^T and PV single pass fp16.
// Row = 128 fp16 = 256 B + 16 pad = 272 B stride (17 x 16B -> conflict-free).
// =====================================================================
#define FROWB 272
#define FPLANE (128*FROWB)          // 34816 B
#define FSTAGE (2*FPLANE)           // 69632 B (K plane + V plane)
#define FLASH_SMEM (3*FSTAGE + 16)  // 208912 B (16 B for job broadcast)
#define NJOBS 512

__global__ void __launch_bounds__(256) flash_kernel()
{
  extern __shared__ char smem[];
  const uint32_t sb = s_addr(smem);
  uint32_t* sjob = reinterpret_cast<uint32_t*>(smem + 3*FSTAGE);
  const int tid = threadIdx.x, lane = tid & 31, warp = tid >> 5;
  const int g = lane >> 2, t4 = lane & 3;

  for (;;){
    if (tid == 0) *sjob = atomicAdd(&g_job, 1u);
    __syncthreads();
    const uint32_t j = *sjob;
    if (j >= NJOBS) break;
    const int qt = 15 - (int)(j >> 5);       // heavy tiles first (LPT)
    const int h  = (int)(j & 31);
    const int q0 = qt*128, kvh = h >> 2;

    // ---- stage Q plane (128 rows x 272 B = 34816 B, fits buf0 K plane) ----
    #pragma unroll
    for (int i = 0; i < 8; i++){
      int idx = i*256 + tid;
      int r = idx >> 4, c = idx & 15;
      const __half* src = g_Q + (size_t)(q0 + r)*4096 + h*128 + c*8;
      *reinterpret_cast<uint4*>(smem + r*FROWB + c*16) =
          *reinterpret_cast<const uint4*>(src);
    }
    __syncthreads();

    uint32_t qh[8][4];
    {
      uint32_t rowb = (uint32_t)(warp*16 + (lane & 15))*FROWB + ((lane >> 4) << 4);
      #pragma unroll
      for (int kk = 0; kk < 8; kk++)
        ldm_x4(sb + rowb + kk*32, qh[kk][0], qh[kk][1], qh[kk][2], qh[kk][3]);
    }
    __syncthreads();   // all Q reads done before cp.async reuses buffer 0

    float o[16][4];
    #pragma unroll
    for (int i = 0; i < 16; i++){ o[i][0]=0.f; o[i][1]=0.f; o[i][2]=0.f; o[i][3]=0.f; }
    float rm0 = -1e30f, rm1 = -1e30f;
    float rl0 = 0.f,    rl1 = 0.f;

    const int nkv = qt + 1;   // 128-wide KV tiles

    auto issue = [&](int kt){
      const uint32_t s0 = sb + (uint32_t)(kt % 3)*FSTAGE;
      const int kv0 = kt*128;
      #pragma unroll
      for (int i = 0; i < 16; i++){   // K,V: 2 planes x 128 rows x 16 chunks
        int idx = i*256 + tid;
        int p = idx >> 11, r = (idx >> 4) & 127, c = idx & 15;
        const __half* base = p ? g_V : g_K;
        cp16(s0 + (uint32_t)p*FPLANE + r*FROWB + c*16,
             base + (size_t)(kv0 + r)*1024 + kvh*128 + c*8);
      }
    };

    issue(0); cp_commit();
    issue(1); cp_commit();

    for (int kvt = 0; kvt < nkv; kvt++){
      const int kv0 = kvt*128;
      cp_wait1();
      __syncthreads();
      if (kvt + 2 < nkv) issue(kvt + 2);   // prefetch BEFORE compute
      cp_commit();
      const uint32_t s0 = sb + (uint32_t)(kvt % 3)*FSTAGE;
      const uint32_t kB = s0, vB = s0 + FPLANE;

      // ---- S = Q K^T (single pass, 128 kv cols) ----
      float s[16][4];
      #pragma unroll
      for (int i = 0; i < 16; i++){ s[i][0]=0.f; s[i][1]=0.f; s[i][2]=0.f; s[i][3]=0.f; }
      {
        const int nr = (lane & 7) + ((lane >> 4) << 3);
        #pragma unroll
        for (int kk = 0; kk < 8; kk++){
          const uint32_t ccb = kk*32 + (((lane >> 3) & 1) << 4);
          #pragma unroll
          for (int g4 = 0; g4 < 8; g4++){
            uint32_t bh[2][2];
            uint32_t off = (uint32_t)(g4*16 + nr)*FROWB + ccb;
            ldm_x4(kB + off, bh[0][0], bh[0][1], bh[1][0], bh[1][1]);
            mma_h(s[g4*2],     qh[kk], bh[0]);
            mma_h(s[g4*2 + 1], qh[kk], bh[1]);
          }
        }
      }

      // ---- causal mask ----
      if (kv0 + 127 > q0 + warp*16){
        #pragma unroll
        for (int nt = 0; nt < 16; nt++){
          int kvb = kv0 + nt*8 + t4*2;
          #pragma unroll
          for (int jj = 0; jj < 4; jj++){
            int kv = kvb + (jj & 1);
            int rw = q0 + warp*16 + g + ((jj >> 1) << 3);
            if (kv > rw) s[nt][jj] = -1e30f;
          }
        }
      }

      // ---- online softmax ----
      float mt0 = -1e30f, mt1 = -1e30f;
      #pragma unroll
      for (int nt = 0; nt < 16; nt++){
        mt0 = fmaxf(mt0, fmaxf(s[nt][0], s[nt][1]));
        mt1 = fmaxf(mt1, fmaxf(s[nt][2], s[nt][3]));
      }
      mt0 = fmaxf(mt0, __shfl_xor_sync(0xffffffffu, mt0, 1));
      mt0 = fmaxf(mt0, __shfl_xor_sync(0xffffffffu, mt0, 2));
      mt1 = fmaxf(mt1, __shfl_xor_sync(0xffffffffu, mt1, 1));
      mt1 = fmaxf(mt1, __shfl_xor_sync(0xffffffffu, mt1, 2));
      float mn0 = fmaxf(rm0, mt0), mn1 = fmaxf(rm1, mt1);
      float f0 = __expf(rm0 - mn0), f1 = __expf(rm1 - mn1);
      rm0 = mn0; rm1 = mn1;
      float ps0 = 0.f, ps1 = 0.f;
      #pragma unroll
      for (int nt = 0; nt < 16; nt++){
        s[nt][0] = __expf(s[nt][0] - mn0); ps0 += s[nt][0];
        s[nt][1] = __expf(s[nt][1] - mn0); ps0 += s[nt][1];
        s[nt][2] = __expf(s[nt][2] - mn1); ps1 += s[nt][2];
        s[nt][3] = __expf(s[nt][3] - mn1); ps1 += s[nt][3];
      }
      rl0 = rl0*f0 + ps0;
      rl1 = rl1*f1 + ps1;
      #pragma unroll
      for (int d = 0; d < 16; d++){
        o[d][0] *= f0; o[d][1] *= f0; o[d][2] *= f1; o[d][3] *= f1;
      }

      // ---- repack P as fp16x2 A-fragments (registers) ----
      uint32_t pah[8][4];
      #pragma unroll
      for (int k2 = 0; k2 < 8; k2++){
        pah[k2][0] = pk2h(__float2half_rn(s[2*k2][0]),   __float2half_rn(s[2*k2][1]));
        pah[k2][1] = pk2h(__float2half_rn(s[2*k2][2]),   __float2half_rn(s[2*k2][3]));
        pah[k2][2] = pk2h(__float2half_rn(s[2*k2+1][0]), __float2half_rn(s[2*k2+1][1]));
        pah[k2][3] = pk2h(__float2half_rn(s[2*k2+1][2]), __float2half_rn(s[2*k2+1][3]));
      }

      // ---- O += P V (single pass, 128 kv rows) ----
      #pragma unroll
      for (int k2 = 0; k2 < 8; k2++){
        uint32_t vrowb = (uint32_t)(k2*16 + (lane & 7) + (((lane >> 3) & 1) << 3))*FROWB
                       + (((lane >> 4) & 1) << 4);
        #pragma unroll
        for (int dg = 0; dg < 8; dg++){
          uint32_t vh[2][2];
          ldm_x4t(vB + vrowb + dg*32, vh[0][0], vh[0][1], vh[1][0], vh[1][1]);
          mma_h(o[dg*2],     pah[k2], vh[0]);
          mma_h(o[dg*2 + 1], pah[k2], vh[1]);
        }
      }
      // no end-of-loop sync: next iteration's cp_wait + syncthreads orders the
      // kvt+3 overwrite of buf kvt%3 against all threads' compute(kvt).
    }

    // ---- finalize: O /= l, write single fp16 plane ----
    rl0 += __shfl_xor_sync(0xffffffffu, rl0, 1);
    rl0 += __shfl_xor_sync(0xffffffffu, rl0, 2);
    rl1 += __shfl_xor_sync(0xffffffffu, rl1, 1);
    rl1 += __shfl_xor_sync(0xffffffffu, rl1, 2);
    float inv0 = 1.f/rl0, inv1 = 1.f/rl1;
    int row = q0 + warp*16 + g;
    #pragma unroll
    for (int dg = 0; dg < 16; dg++){
      int c = h*128 + dg*8 + t4*2;
      uint32_t ph0 = pk2h(__float2half_rn(o[dg][0]*inv0), __float2half_rn(o[dg][1]*inv0));
      uint32_t ph1 = pk2h(__float2half_rn(o[dg][2]*inv1), __float2half_rn(o[dg][3]*inv1));
      *reinterpret_cast<uint32_t*>(&g_AO[(size_t)row*4096 + c])     = ph0;
      *reinterpret_cast<uint32_t*>(&g_AO[(size_t)(row+8)*4096 + c]) = ph1;
    }

    cp_wait0();          // drain pending (empty) groups before next job
    __syncthreads();     // all smem reads done before next job's Q staging
  }
}

// =====================================================================
// launch
// =====================================================================
extern "C" void kernel_launch(void* const* d_in, const int* in_sizes, int n_in,
                              void* d_out, int out_size)
{
  (void)in_sizes; (void)n_in; (void)out_size;
  const float* x  = (const float*)d_in[0];
  const float* fc = (const float*)d_in[2];
  const float* wq = (const float*)d_in[3];
  const float* wk = (const float*)d_in[4];
  const float* wv = (const float*)d_in[5];
  const float* wo = (const float*)d_in[6];
  float* out = (float*)d_out;

  __half *X, *Wt, *WOt, *AO;
  void* jobp;
  cudaGetSymbolAddress((void**)&X,   g_X);
  cudaGetSymbolAddress((void**)&Wt,  g_Wt);
  cudaGetSymbolAddress((void**)&WOt, g_WOt);
  cudaGetSymbolAddress((void**)&AO,  g_AO);
  cudaGetSymbolAddress(&jobp, g_job);

  cudaFuncSetAttribute(gemm_ca<0>, cudaFuncAttributeMaxDynamicSharedMemorySize, GEMM_SMEM);
  cudaFuncSetAttribute(gemm_ca<1>, cudaFuncAttributeMaxDynamicSharedMemorySize, GEMM_SMEM);
  cudaFuncSetAttribute(flash_kernel, cudaFuncAttributeMaxDynamicSharedMemorySize, FLASH_SMEM);

  // conversions
  conv_x<<<4096, 256>>>(x);
  tconv_all<<<dim3(160, 64), 256>>>(wq, wk, wv, wo);

  // fused QKV projection + RoPE + fp16 convert (writes g_Q/g_K/g_V)
  cudaMemsetAsync(jobp, 0, sizeof(uint32_t));
  gemm_ca<1><<<296, 256, GEMM_SMEM>>>(X, Wt, nullptr, fc, 6144, 4096, 768, 48);

  // persistent attention
  cudaMemsetAsync(jobp, 0, sizeof(uint32_t));
  flash_kernel<<<148, 256, FLASH_SMEM>>>();

  // output projection
  cudaMemsetAsync(jobp, 0, sizeof(uint32_t));
  gemm_ca<0><<<296, 256, GEMM_SMEM>>>(AO, WOt, out, nullptr, 4096, 4096, 512, 32);
}